// round 13
// baseline (speedup 1.0000x reference)
#include <cuda_runtime.h>
#include <cstdint>
#include <math.h>

#define NN 32
#define CC 128
#define SSZ 4096
#define KK 64
#define NCHUNK 9            // chunk 0: 8 subtiles, chunks 1-8: 7 subtiles
#define SUBT 64
#define THREADS 256

// padded row lengths (floats)
#define XPADF 136
#define APADF 72

// smem byte offsets (90880 B total -> 2 blocks/SM)
#define OFF_XS0  0          // xs buf0 [64 p][136] : 34816
#define OFF_XS1  34816      // xs buf1            : 34816
#define OFF_AS   69632      // as [64 k][72]      : 18432
#define OFF_RED  88064      // 256 floats
#define OFF_BS   89088      // 64 floats (conv_b)
#define OFF_SMS  89344      // 128 floats (sum exchange)
#define OFF_ASR  89856      // 256 floats
#define SMEM_BYTES 90880

// scratch (no allocation allowed)
__device__ float g_vlad_part[NN * NCHUNK * KK * CC];   // [n][ch][k][c]
__device__ float g_asum_part[NN * NCHUNK * KK];
__device__ float g_outk[NN * KK * CC];                 // scaled vlad rows
__device__ float4 g_wfrag[2048];                       // packed W B-frags, 32KB

// ---------------------------------------------------------------------------
__device__ __forceinline__ float tf32r(float x) {
    float r;
    asm("cvt.rna.tf32.f32 %0, %1;" : "=f"(r) : "f"(x));
    return r;
}
__device__ __forceinline__ void mma_tf32(float* d, uint32_t a0, uint32_t a1,
                                         uint32_t a2, uint32_t a3,
                                         uint32_t b0, uint32_t b1) {
    asm volatile(
        "mma.sync.aligned.m16n8k8.row.col.f32.tf32.tf32.f32 "
        "{%0,%1,%2,%3}, {%4,%5,%6,%7}, {%8,%9}, {%0,%1,%2,%3};"
        : "+f"(d[0]), "+f"(d[1]), "+f"(d[2]), "+f"(d[3])
        : "r"(a0), "r"(a1), "r"(a2), "r"(a3), "r"(b0), "r"(b1));
}
// column permutation within 8-blocks: logical j -> position 2*(j&3) + (j>>2)
__device__ __forceinline__ int perm8(int j) { return 2 * (j & 3) + ((j >> 2) & 1); }
__device__ __forceinline__ uint32_t fu(float v) { return __float_as_uint(v); }

// ---------------------------------------------------------------------------
// Kernel 0: pack W into GEMM1 B-fragment order (tf32 rna-rounded).
// idx = ((kh*16 + ks)*2 + nbp)*32 + lane  =  kh*1024 + ks*64 + nbp*32 + lane
// ---------------------------------------------------------------------------
__global__ void netvlad_winit(const float* __restrict__ w)
{
    const int idx  = blockIdx.x * 256 + threadIdx.x;   // 0..2047
    const int lane = idx & 31;
    const int g    = lane >> 2, tg = lane & 3;
    const int t    = idx >> 5;                         // 0..63
    const int nbp  = t & 1;
    const int ks   = (t >> 1) & 15;
    const int kh   = t >> 5;
    const int k0   = kh * 32 + nbp * 16 + g;
    const int c1   = ks * 8 + tg, c2 = c1 + 4;
    g_wfrag[idx] = make_float4(tf32r(w[k0 * CC + c1]),
                               tf32r(w[k0 * CC + c2]),
                               tf32r(w[(k0 + 8) * CC + c1]),
                               tf32r(w[(k0 + 8) * CC + c2]));
}

// ---------------------------------------------------------------------------
// Kernel 1: per (n, chunk).  Double-buffered XS (no WAR barrier), W from
// L1-resident g_wfrag, prefetch issued post-GEMM1.  2 CTAs/SM.
// ---------------------------------------------------------------------------
__global__ void __launch_bounds__(THREADS, 2)
netvlad_k1(const float* __restrict__ x,
           const float* __restrict__ conv_b)
{
    extern __shared__ char smem[];
    float* red  = (float*)(smem + OFF_RED);
    float* bs   = (float*)(smem + OFF_BS);
    float* sms  = (float*)(smem + OFF_SMS);
    float* asr  = (float*)(smem + OFF_ASR);

    const int tid  = threadIdx.x;
    const int wid  = tid >> 5, lane = tid & 31;
    const int g    = lane >> 2, tg = lane & 3;
    const int tgh  = tg >> 1;            // store-order flip selector
    const int pg   = perm8(g);
    const int ch   = blockIdx.x, n = blockIdx.y;
    const int p    = tid & 63;           // pixel within subtile
    const int c0   = (tid >> 6) * 32;    // channel quarter
    // GEMM1 roles: 4 p-strips (16) x 2 k-halves (32)
    const int pw   = wid & 3,  kh = wid >> 2;
    const int p0   = pw * 16,  kb = kh * 32;
    // GEMM2 roles: 2 k-strips (32) x 4 c-quarters (32)
    const int mw   = wid & 1,  nh = wid >> 1;

    const int nsub = (ch == 0) ? 8 : 7;
    const int ps   = (ch == 0) ? 0 : (64 + 448 * ch);   // chunk pixel start

    const float* xb = x + ((size_t)(n * CC + c0)) * SSZ + ps + p;
    const float4* wf = g_wfrag + kh * 1024 + lane;      // FIXED: stride 1024

    // ---- prologue: loads for subtile 0 ----
    float xv[32];
#pragma unroll
    for (int i = 0; i < 32; i++) xv[i] = xb[(size_t)i * SSZ];

    if (tid < KK) bs[tid] = conv_b[tid];

    float vacc[2][4][4];
#pragma unroll
    for (int m = 0; m < 2; m++)
#pragma unroll
        for (int i = 0; i < 4; i++)
#pragma unroll
            for (int j = 0; j < 4; j++) vacc[m][i][j] = 0.f;
    float ap[8];
#pragma unroll
    for (int i = 0; i < 8; i++) ap[i] = 0.f;

#pragma unroll 1
    for (int st = 0; st < nsub; ++st) {
        char* xso = smem + ((st & 1) ? OFF_XS1 : OFF_XS0);

        // ---- sumsq + store raw x (tf32 rna) into buffer st&1 ----
        // (no barrier needed: buffer st&1 was last read two S_B/S_C pairs ago)
        float ssum = 0.f;
#pragma unroll
        for (int i = 0; i < 32; i++) ssum += xv[i] * xv[i];
        {
            char* rowp = xso + (p * XPADF + c0) * 4;
#pragma unroll
            for (int b = 0; b < 4; b++) {
                float4 s1 = make_float4(tf32r(xv[8*b+0]), tf32r(xv[8*b+4]),
                                        tf32r(xv[8*b+1]), tf32r(xv[8*b+5]));
                float4 s2 = make_float4(tf32r(xv[8*b+2]), tf32r(xv[8*b+6]),
                                        tf32r(xv[8*b+3]), tf32r(xv[8*b+7]));
                *(float4*)(rowp + b * 32)      = s1;
                *(float4*)(rowp + b * 32 + 16) = s2;
            }
        }
        red[tid] = ssum;
        __syncthreads();     // S_B: xs(st) + red visible; prev AS reads done

        // ---- GEMM1: lac[p0..p0+15][kb..kb+31] = W · x_tf32 ----
        float lac[4][4];
#pragma unroll
        for (int i = 0; i < 4; i++)
#pragma unroll
            for (int j = 0; j < 4; j++) lac[i][j] = 0.f;
#pragma unroll 4
        for (int ks = 0; ks < 16; ks++) {
            uint2 aLo = *(uint2*)(xso + (((p0 + g)     * XPADF) + ks * 8 + 2 * tg) * 4);
            uint2 aHi = *(uint2*)(xso + (((p0 + g + 8) * XPADF) + ks * 8 + 2 * tg) * 4);
            float4 w01 = __ldg(&wf[ks * 64]);
            float4 w23 = __ldg(&wf[ks * 64 + 32]);
            mma_tf32(lac[0], aLo.x, aHi.x, aLo.y, aHi.y, fu(w01.x), fu(w01.y));
            mma_tf32(lac[1], aLo.x, aHi.x, aLo.y, aHi.y, fu(w01.z), fu(w01.w));
            mma_tf32(lac[2], aLo.x, aHi.x, aLo.y, aHi.y, fu(w23.x), fu(w23.y));
            mma_tf32(lac[3], aLo.x, aHi.x, aLo.y, aHi.y, fu(w23.z), fu(w23.w));
        }

        // ---- prefetch next subtile (xv dead during GEMM1; refill now) ----
        if (st + 1 < nsub) {
            const float* xn = xb + (st + 1) * SUBT;
#pragma unroll
            for (int i = 0; i < 32; i++) xv[i] = xn[(size_t)i * SSZ];
        }

        // ---- per-row inverse norms ----
        const int r0 = p0 + g, r1 = p0 + g + 8;
        const float rv0 = 1.0f / fmaxf(
            sqrtf(red[r0] + red[r0 + 64] + red[r0 + 128] + red[r0 + 192]), 1e-12f);
        const float rv1 = 1.0f / fmaxf(
            sqrtf(red[r1] + red[r1 + 64] + red[r1 + 128] + red[r1 + 192]), 1e-12f);

        // ---- softmax over full k (pairwise exchange, named barrier) ----
        {
            float v0[8], v1[8];
            float s0a = 0.f, s1a = 0.f;
#pragma unroll
            for (int i = 0; i < 8; i++) {
                int nb = i >> 1, j = i & 1;
                const float bv = bs[kb + nb * 8 + tg * 2 + j];
                v0[i] = __expf(lac[nb][j]     * rv0 + bv);  s0a += v0[i];
                v1[i] = __expf(lac[nb][2 + j] * rv1 + bv);  s1a += v1[i];
            }
            s0a += __shfl_xor_sync(0xffffffffu, s0a, 1);
            s0a += __shfl_xor_sync(0xffffffffu, s0a, 2);
            s1a += __shfl_xor_sync(0xffffffffu, s1a, 1);
            s1a += __shfl_xor_sync(0xffffffffu, s1a, 2);
            if (tg == 0) {
                sms[kh * 64 + r0] = s0a;
                sms[kh * 64 + r1] = s1a;
            }
            asm volatile("bar.sync %0, 64;" :: "r"(1 + pw) : "memory");
            const float ir0 = 1.0f / (sms[r0] + sms[64 + r0]);
            const float ir1 = 1.0f / (sms[r1] + sms[64 + r1]);

#pragma unroll
            for (int nt = 0; nt < 4; nt++) {
                float a00 = v0[nt * 2 + 0] * ir0;
                float a01 = v0[nt * 2 + 1] * ir0;
                float a10 = v1[nt * 2 + 0] * ir1;
                float a11 = v1[nt * 2 + 1] * ir1;
                ap[nt * 2 + 0] += a00 + a10;
                ap[nt * 2 + 1] += a01 + a11;
                const int kA = kb + nt * 8 + tg * 2 + tgh;
                const int kB = kb + nt * 8 + tg * 2 + (1 - tgh);
                const float sA0 = tf32r((tgh ? a01 : a00) * rv0);
                const float sA1 = tf32r((tgh ? a11 : a10) * rv1);
                const float sB0 = tf32r((tgh ? a00 : a01) * rv0);
                const float sB1 = tf32r((tgh ? a10 : a11) * rv1);
                *(float*)(smem + OFF_AS + (kA * APADF + p0 + pg) * 4)     = sA0;
                *(float*)(smem + OFF_AS + (kA * APADF + p0 + 8 + pg) * 4) = sA1;
                *(float*)(smem + OFF_AS + (kB * APADF + p0 + pg) * 4)     = sB0;
                *(float*)(smem + OFF_AS + (kB * APADF + p0 + 8 + pg) * 4) = sB1;
            }
        }
        __syncthreads();     // S_C: as visible to GEMM2 consumers

        // ---- GEMM2: vlad[mw*32..+31][nh*32..+31] += a_s · x ----
#pragma unroll
        for (int ks = 0; ks < 8; ks++) {
            uint2 aL0 = *(uint2*)(smem + OFF_AS + (((mw * 32 + g)      * APADF) + ks * 8 + 2 * tg) * 4);
            uint2 aH0 = *(uint2*)(smem + OFF_AS + (((mw * 32 + g + 8)  * APADF) + ks * 8 + 2 * tg) * 4);
            uint2 aL1 = *(uint2*)(smem + OFF_AS + (((mw * 32 + g + 16) * APADF) + ks * 8 + 2 * tg) * 4);
            uint2 aH1 = *(uint2*)(smem + OFF_AS + (((mw * 32 + g + 24) * APADF) + ks * 8 + 2 * tg) * 4);
#pragma unroll
            for (int nb = 0; nb < 4; nb++) {
                const int col = nh * 32 + nb * 8 + pg;
                uint32_t b0 = *(uint32_t*)(xso + (((ks * 8 + tg)     * XPADF) + col) * 4);
                uint32_t b1 = *(uint32_t*)(xso + (((ks * 8 + tg + 4) * XPADF) + col) * 4);
                mma_tf32(vacc[0][nb], aL0.x, aH0.x, aL0.y, aH0.y, b0, b1);
                mma_tf32(vacc[1][nb], aL1.x, aH1.x, aL1.y, aH1.y, b0, b1);
            }
        }
    }

    // ---- write vlad partials ----
    {
        float* vp = g_vlad_part + (size_t)(n * NCHUNK + ch) * KK * CC;
#pragma unroll
        for (int m = 0; m < 2; m++) {
            const int k0 = mw * 32 + m * 16 + g;
#pragma unroll
            for (int nt = 0; nt < 4; nt++) {
                const int c = nh * 32 + nt * 8 + tg * 2;
                *(float2*)&vp[k0 * CC + c]       = make_float2(vacc[m][nt][0], vacc[m][nt][1]);
                *(float2*)&vp[(k0 + 8) * CC + c] = make_float2(vacc[m][nt][2], vacc[m][nt][3]);
            }
        }
    }
    // ---- asum reduce ----
#pragma unroll
    for (int i = 0; i < 8; i++) {
        ap[i] += __shfl_xor_sync(0xffffffffu, ap[i], 4);
        ap[i] += __shfl_xor_sync(0xffffffffu, ap[i], 8);
        ap[i] += __shfl_xor_sync(0xffffffffu, ap[i], 16);
    }
    if (lane < 4) {   // lane == tg
#pragma unroll
        for (int i = 0; i < 8; i++)
            asr[wid * 32 + (i >> 1) * 8 + lane * 2 + (i & 1)] = ap[i];
    }
    __syncthreads();
    if (tid < KK) {
        const int kh2 = tid >> 5, lk = tid & 31;
        float t = 0.f;
#pragma unroll
        for (int pw2 = 0; pw2 < 4; pw2++)
            t += asr[(kh2 * 4 + pw2) * 32 + lk];
        g_asum_part[(n * NCHUNK + ch) * KK + tid] = t;
    }
}

// ---------------------------------------------------------------------------
// Kernel 2a: one block per (n,k). Reduce chunk partials, centroid subtract,
// intra-normalize, scale by fc_w.
// ---------------------------------------------------------------------------
__global__ void __launch_bounds__(128)
netvlad_k2a(const float* __restrict__ centroids,
            const float* __restrict__ fc_w)
{
    const int k = blockIdx.x;       // 0..63
    const int n = blockIdx.y;       // 0..31
    const int c = threadIdx.x;      // 0..127
    __shared__ float sred[4];

    float asum = 0.f;
#pragma unroll
    for (int chn = 0; chn < NCHUNK; chn++)
        asum += __ldg(&g_asum_part[(n * NCHUNK + chn) * KK + k]);

    float v = -asum * centroids[k * CC + c];
#pragma unroll
    for (int chn = 0; chn < NCHUNK; chn++)
        v += g_vlad_part[((size_t)(n * NCHUNK + chn) * KK + k) * CC + c];

    float ss = v * v;
#pragma unroll
    for (int off = 16; off > 0; off >>= 1)
        ss += __shfl_xor_sync(0xffffffffu, ss, off);
    if ((c & 31) == 0) sred[c >> 5] = ss;
    __syncthreads();
    const float tot = sred[0] + sred[1] + sred[2] + sred[3];
    const float sc = (1.0f / fmaxf(sqrtf(tot), 1e-12f)) * fc_w[k];
    g_outk[((size_t)n * KK + k) * CC + c] = v * sc;
}

// ---------------------------------------------------------------------------
// Kernel 2b: out[n][c] = sum_k g_outk[n][k][c].
// ---------------------------------------------------------------------------
__global__ void __launch_bounds__(128)
netvlad_k2b(float* __restrict__ out)
{
    __shared__ float accs[4][132];
    const int n    = blockIdx.x;
    const int tid  = threadIdx.x;
    const int wid  = tid >> 5, lane = tid & 31;
    const int c0   = lane * 4;

    float4 acc = make_float4(0.f, 0.f, 0.f, 0.f);
    const float* bp = g_outk + (size_t)n * KK * CC + c0;
#pragma unroll
    for (int kk = 0; kk < 16; kk++) {
        const float4 v = *(const float4*)&bp[(wid * 16 + kk) * CC];
        acc.x += v.x; acc.y += v.y; acc.z += v.z; acc.w += v.w;
    }
    *(float4*)&accs[wid][c0] = acc;
    __syncthreads();
    if (tid < CC)
        out[n * CC + tid] = accs[0][tid] + accs[1][tid]
                          + accs[2][tid] + accs[3][tid];
}

// ---------------------------------------------------------------------------
extern "C" void kernel_launch(void* const* d_in, const int* in_sizes, int n_in,
                              void* d_out, int out_size)
{
    const float* x      = (const float*)d_in[0];  // [32,128,64,64]
    const float* conv_w = (const float*)d_in[1];  // [64,128]
    const float* conv_b = (const float*)d_in[2];  // [64]
    const float* cent   = (const float*)d_in[3];  // [64,128]
    const float* fc_w   = (const float*)d_in[4];  // [1,64]
    float* out = (float*)d_out;                   // [32,128]

    cudaFuncSetAttribute(netvlad_k1,
                         cudaFuncAttributeMaxDynamicSharedMemorySize,
                         SMEM_BYTES);

    netvlad_winit<<<8, 256>>>(conv_w);

    dim3 g1(NCHUNK, NN);        // 288 blocks -> balanced 2/SM
    netvlad_k1<<<g1, THREADS, SMEM_BYTES>>>(x, conv_b);

    dim3 g2a(KK, NN);
    netvlad_k2a<<<g2a, 128>>>(cent, fc_w);

    netvlad_k2b<<<NN, 128>>>(out);
}

// round 14
// speedup vs baseline: 1.1455x; 1.1455x over previous
#include <cuda_runtime.h>
#include <cstdint>
#include <math.h>

#define NN 32
#define CC 128
#define SSZ 4096
#define KK 64
#define NCHUNK 9            // chunk 0: 8 subtiles, chunks 1-8: 7 subtiles
#define SUBT 64
#define THREADS 256

// padded row lengths (floats)
#define XPADF 136
#define APADF 72

// smem byte offsets (90880 B total -> 2 blocks/SM)
#define OFF_XS0  0          // xs buf0 [64 p][136] : 34816
#define OFF_XS1  34816      // xs buf1            : 34816
#define OFF_AS   69632      // as [64 k][72]      : 18432
#define OFF_RED  88064      // 256 floats
#define OFF_BS   89088      // 64 floats (conv_b)
#define OFF_SMS  89344      // 128 floats (sum exchange)
#define OFF_ASR  89856      // 256 floats
#define SMEM_BYTES 90880

// scratch (no allocation allowed)
__device__ float g_vlad_part[NN * NCHUNK * KK * CC];   // [n][ch][k][c]
__device__ float g_asum_part[NN * NCHUNK * KK];
__device__ float g_outk[NN * KK * CC];                 // scaled vlad rows
__device__ float4 g_wfrag[2048];                       // packed W B-frags, 32KB

// ---------------------------------------------------------------------------
__device__ __forceinline__ float tf32r(float x) {
    float r;
    asm("cvt.rna.tf32.f32 %0, %1;" : "=f"(r) : "f"(x));
    return r;
}
__device__ __forceinline__ void mma_tf32(float* d, uint32_t a0, uint32_t a1,
                                         uint32_t a2, uint32_t a3,
                                         uint32_t b0, uint32_t b1) {
    asm volatile(
        "mma.sync.aligned.m16n8k8.row.col.f32.tf32.tf32.f32 "
        "{%0,%1,%2,%3}, {%4,%5,%6,%7}, {%8,%9}, {%0,%1,%2,%3};"
        : "+f"(d[0]), "+f"(d[1]), "+f"(d[2]), "+f"(d[3])
        : "r"(a0), "r"(a1), "r"(a2), "r"(a3), "r"(b0), "r"(b1));
}
// column permutation within 8-blocks: logical j -> position 2*(j&3) + (j>>2)
__device__ __forceinline__ int perm8(int j) { return 2 * (j & 3) + ((j >> 2) & 1); }
__device__ __forceinline__ uint32_t fu(float v) { return __float_as_uint(v); }

// ---------------------------------------------------------------------------
// Kernel 0: pack W into GEMM1 B-fragment order (tf32 rna-rounded).
// idx = kh*1024 + ks*64 + nbp*32 + lane
// ---------------------------------------------------------------------------
__global__ void netvlad_winit(const float* __restrict__ w)
{
    const int idx  = blockIdx.x * 256 + threadIdx.x;   // 0..2047
    const int lane = idx & 31;
    const int g    = lane >> 2, tg = lane & 3;
    const int t    = idx >> 5;                         // 0..63
    const int nbp  = t & 1;
    const int ks   = (t >> 1) & 15;
    const int kh   = t >> 5;
    const int k0   = kh * 32 + nbp * 16 + g;
    const int c1   = ks * 8 + tg, c2 = c1 + 4;
    g_wfrag[idx] = make_float4(tf32r(w[k0 * CC + c1]),
                               tf32r(w[k0 * CC + c2]),
                               tf32r(w[(k0 + 8) * CC + c1]),
                               tf32r(w[(k0 + 8) * CC + c2]));
}

// ---------------------------------------------------------------------------
// Kernel 1: per (n, chunk).  Double-buffered XS (2 barriers/subtile),
// W from L1-resident g_wfrag; x loads use .cg (bypass L1) so W stays hot.
// ---------------------------------------------------------------------------
__global__ void __launch_bounds__(THREADS, 2)
netvlad_k1(const float* __restrict__ x,
           const float* __restrict__ conv_b)
{
    extern __shared__ char smem[];
    float* red  = (float*)(smem + OFF_RED);
    float* bs   = (float*)(smem + OFF_BS);
    float* sms  = (float*)(smem + OFF_SMS);
    float* asr  = (float*)(smem + OFF_ASR);

    const int tid  = threadIdx.x;
    const int wid  = tid >> 5, lane = tid & 31;
    const int g    = lane >> 2, tg = lane & 3;
    const int tgh  = tg >> 1;            // store-order flip selector
    const int pg   = perm8(g);
    const int ch   = blockIdx.x, n = blockIdx.y;
    const int p    = tid & 63;           // pixel within subtile
    const int c0   = (tid >> 6) * 32;    // channel quarter
    // GEMM1 roles: 4 p-strips (16) x 2 k-halves (32)
    const int pw   = wid & 3,  kh = wid >> 2;
    const int p0   = pw * 16,  kb = kh * 32;
    // GEMM2 roles: 2 k-strips (32) x 4 c-quarters (32)
    const int mw   = wid & 1,  nh = wid >> 1;

    const int nsub = (ch == 0) ? 8 : 7;
    const int ps   = (ch == 0) ? 0 : (64 + 448 * ch);   // chunk pixel start

    const float* xb = x + ((size_t)(n * CC + c0)) * SSZ + ps + p;
    const float4* wf = g_wfrag + kh * 1024 + lane;

    // ---- prologue: loads for subtile 0 (L1-bypass) ----
    float xv[32];
#pragma unroll
    for (int i = 0; i < 32; i++) xv[i] = __ldcg(&xb[(size_t)i * SSZ]);

    if (tid < KK) bs[tid] = conv_b[tid];

    float vacc[2][4][4];
#pragma unroll
    for (int m = 0; m < 2; m++)
#pragma unroll
        for (int i = 0; i < 4; i++)
#pragma unroll
            for (int j = 0; j < 4; j++) vacc[m][i][j] = 0.f;
    float ap[8];
#pragma unroll
    for (int i = 0; i < 8; i++) ap[i] = 0.f;

#pragma unroll 1
    for (int st = 0; st < nsub; ++st) {
        char* xso = smem + ((st & 1) ? OFF_XS1 : OFF_XS0);

        // ---- sumsq + store raw x (tf32 rna) into buffer st&1 ----
        float ssum = 0.f;
#pragma unroll
        for (int i = 0; i < 32; i++) ssum += xv[i] * xv[i];
        {
            char* rowp = xso + (p * XPADF + c0) * 4;
#pragma unroll
            for (int b = 0; b < 4; b++) {
                float4 s1 = make_float4(tf32r(xv[8*b+0]), tf32r(xv[8*b+4]),
                                        tf32r(xv[8*b+1]), tf32r(xv[8*b+5]));
                float4 s2 = make_float4(tf32r(xv[8*b+2]), tf32r(xv[8*b+6]),
                                        tf32r(xv[8*b+3]), tf32r(xv[8*b+7]));
                *(float4*)(rowp + b * 32)      = s1;
                *(float4*)(rowp + b * 32 + 16) = s2;
            }
        }
        red[tid] = ssum;
        __syncthreads();     // S_B: xs(st) + red visible; prev AS reads done

        // ---- GEMM1: lac[p0..p0+15][kb..kb+31] = W · x_tf32 ----
        float lac[4][4];
#pragma unroll
        for (int i = 0; i < 4; i++)
#pragma unroll
            for (int j = 0; j < 4; j++) lac[i][j] = 0.f;
#pragma unroll 4
        for (int ks = 0; ks < 16; ks++) {
            uint2 aLo = *(uint2*)(xso + (((p0 + g)     * XPADF) + ks * 8 + 2 * tg) * 4);
            uint2 aHi = *(uint2*)(xso + (((p0 + g + 8) * XPADF) + ks * 8 + 2 * tg) * 4);
            float4 w01 = __ldg(&wf[ks * 64]);
            float4 w23 = __ldg(&wf[ks * 64 + 32]);
            mma_tf32(lac[0], aLo.x, aHi.x, aLo.y, aHi.y, fu(w01.x), fu(w01.y));
            mma_tf32(lac[1], aLo.x, aHi.x, aLo.y, aHi.y, fu(w01.z), fu(w01.w));
            mma_tf32(lac[2], aLo.x, aHi.x, aLo.y, aHi.y, fu(w23.x), fu(w23.y));
            mma_tf32(lac[3], aLo.x, aHi.x, aLo.y, aHi.y, fu(w23.z), fu(w23.w));
        }

        // ---- prefetch next subtile (L1-bypass; hidden by softmax+GEMM2) ----
        if (st + 1 < nsub) {
            const float* xn = xb + (st + 1) * SUBT;
#pragma unroll
            for (int i = 0; i < 32; i++) xv[i] = __ldcg(&xn[(size_t)i * SSZ]);
        }

        // ---- per-row inverse norms ----
        const int r0 = p0 + g, r1 = p0 + g + 8;
        const float rv0 = 1.0f / fmaxf(
            sqrtf(red[r0] + red[r0 + 64] + red[r0 + 128] + red[r0 + 192]), 1e-12f);
        const float rv1 = 1.0f / fmaxf(
            sqrtf(red[r1] + red[r1 + 64] + red[r1 + 128] + red[r1 + 192]), 1e-12f);

        // ---- softmax over full k (pairwise exchange, named barrier) ----
        {
            float v0[8], v1[8];
            float s0a = 0.f, s1a = 0.f;
#pragma unroll
            for (int i = 0; i < 8; i++) {
                int nb = i >> 1, j = i & 1;
                const float bv = bs[kb + nb * 8 + tg * 2 + j];
                v0[i] = __expf(lac[nb][j]     * rv0 + bv);  s0a += v0[i];
                v1[i] = __expf(lac[nb][2 + j] * rv1 + bv);  s1a += v1[i];
            }
            s0a += __shfl_xor_sync(0xffffffffu, s0a, 1);
            s0a += __shfl_xor_sync(0xffffffffu, s0a, 2);
            s1a += __shfl_xor_sync(0xffffffffu, s1a, 1);
            s1a += __shfl_xor_sync(0xffffffffu, s1a, 2);
            if (tg == 0) {
                sms[kh * 64 + r0] = s0a;
                sms[kh * 64 + r1] = s1a;
            }
            asm volatile("bar.sync %0, 64;" :: "r"(1 + pw) : "memory");
            const float ir0 = 1.0f / (sms[r0] + sms[64 + r0]);
            const float ir1 = 1.0f / (sms[r1] + sms[64 + r1]);

#pragma unroll
            for (int nt = 0; nt < 4; nt++) {
                float a00 = v0[nt * 2 + 0] * ir0;
                float a01 = v0[nt * 2 + 1] * ir0;
                float a10 = v1[nt * 2 + 0] * ir1;
                float a11 = v1[nt * 2 + 1] * ir1;
                ap[nt * 2 + 0] += a00 + a10;
                ap[nt * 2 + 1] += a01 + a11;
                const int kA = kb + nt * 8 + tg * 2 + tgh;
                const int kB = kb + nt * 8 + tg * 2 + (1 - tgh);
                const float sA0 = tf32r((tgh ? a01 : a00) * rv0);
                const float sA1 = tf32r((tgh ? a11 : a10) * rv1);
                const float sB0 = tf32r((tgh ? a00 : a01) * rv0);
                const float sB1 = tf32r((tgh ? a10 : a11) * rv1);
                *(float*)(smem + OFF_AS + (kA * APADF + p0 + pg) * 4)     = sA0;
                *(float*)(smem + OFF_AS + (kA * APADF + p0 + 8 + pg) * 4) = sA1;
                *(float*)(smem + OFF_AS + (kB * APADF + p0 + pg) * 4)     = sB0;
                *(float*)(smem + OFF_AS + (kB * APADF + p0 + 8 + pg) * 4) = sB1;
            }
        }
        __syncthreads();     // S_C: as visible to GEMM2 consumers

        // ---- GEMM2: vlad[mw*32..+31][nh*32..+31] += a_s · x ----
#pragma unroll
        for (int ks = 0; ks < 8; ks++) {
            uint2 aL0 = *(uint2*)(smem + OFF_AS + (((mw * 32 + g)      * APADF) + ks * 8 + 2 * tg) * 4);
            uint2 aH0 = *(uint2*)(smem + OFF_AS + (((mw * 32 + g + 8)  * APADF) + ks * 8 + 2 * tg) * 4);
            uint2 aL1 = *(uint2*)(smem + OFF_AS + (((mw * 32 + g + 16) * APADF) + ks * 8 + 2 * tg) * 4);
            uint2 aH1 = *(uint2*)(smem + OFF_AS + (((mw * 32 + g + 24) * APADF) + ks * 8 + 2 * tg) * 4);
#pragma unroll
            for (int nb = 0; nb < 4; nb++) {
                const int col = nh * 32 + nb * 8 + pg;
                uint32_t b0 = *(uint32_t*)(xso + (((ks * 8 + tg)     * XPADF) + col) * 4);
                uint32_t b1 = *(uint32_t*)(xso + (((ks * 8 + tg + 4) * XPADF) + col) * 4);
                mma_tf32(vacc[0][nb], aL0.x, aH0.x, aL0.y, aH0.y, b0, b1);
                mma_tf32(vacc[1][nb], aL1.x, aH1.x, aL1.y, aH1.y, b0, b1);
            }
        }
    }

    // ---- write vlad partials ----
    {
        float* vp = g_vlad_part + (size_t)(n * NCHUNK + ch) * KK * CC;
#pragma unroll
        for (int m = 0; m < 2; m++) {
            const int k0 = mw * 32 + m * 16 + g;
#pragma unroll
            for (int nt = 0; nt < 4; nt++) {
                const int c = nh * 32 + nt * 8 + tg * 2;
                *(float2*)&vp[k0 * CC + c]       = make_float2(vacc[m][nt][0], vacc[m][nt][1]);
                *(float2*)&vp[(k0 + 8) * CC + c] = make_float2(vacc[m][nt][2], vacc[m][nt][3]);
            }
        }
    }
    // ---- asum reduce ----
#pragma unroll
    for (int i = 0; i < 8; i++) {
        ap[i] += __shfl_xor_sync(0xffffffffu, ap[i], 4);
        ap[i] += __shfl_xor_sync(0xffffffffu, ap[i], 8);
        ap[i] += __shfl_xor_sync(0xffffffffu, ap[i], 16);
    }
    if (lane < 4) {   // lane == tg
#pragma unroll
        for (int i = 0; i < 8; i++)
            asr[wid * 32 + (i >> 1) * 8 + lane * 2 + (i & 1)] = ap[i];
    }
    __syncthreads();
    if (tid < KK) {
        const int kh2 = tid >> 5, lk = tid & 31;
        float t = 0.f;
#pragma unroll
        for (int pw2 = 0; pw2 < 4; pw2++)
            t += asr[(kh2 * 4 + pw2) * 32 + lk];
        g_asum_part[(n * NCHUNK + ch) * KK + tid] = t;
    }
}

// ---------------------------------------------------------------------------
// Kernel 2a: one block per (n,k). Reduce chunk partials, centroid subtract,
// intra-normalize, scale by fc_w.
// ---------------------------------------------------------------------------
__global__ void __launch_bounds__(128)
netvlad_k2a(const float* __restrict__ centroids,
            const float* __restrict__ fc_w)
{
    const int k = blockIdx.x;       // 0..63
    const int n = blockIdx.y;       // 0..31
    const int c = threadIdx.x;      // 0..127
    __shared__ float sred[4];

    float asum = 0.f;
#pragma unroll
    for (int chn = 0; chn < NCHUNK; chn++)
        asum += __ldg(&g_asum_part[(n * NCHUNK + chn) * KK + k]);

    float v = -asum * centroids[k * CC + c];
#pragma unroll
    for (int chn = 0; chn < NCHUNK; chn++)
        v += g_vlad_part[((size_t)(n * NCHUNK + chn) * KK + k) * CC + c];

    float ss = v * v;
#pragma unroll
    for (int off = 16; off > 0; off >>= 1)
        ss += __shfl_xor_sync(0xffffffffu, ss, off);
    if ((c & 31) == 0) sred[c >> 5] = ss;
    __syncthreads();
    const float tot = sred[0] + sred[1] + sred[2] + sred[3];
    const float sc = (1.0f / fmaxf(sqrtf(tot), 1e-12f)) * fc_w[k];
    g_outk[((size_t)n * KK + k) * CC + c] = v * sc;
}

// ---------------------------------------------------------------------------
// Kernel 2b: out[n][c] = sum_k g_outk[n][k][c].  128 blocks (4 c-quarters
// per image), coalesced, 16-deep MLP per thread.
// ---------------------------------------------------------------------------
__global__ void __launch_bounds__(128)
netvlad_k2b(float* __restrict__ out)
{
    __shared__ float accs[4][33];
    const int cq = blockIdx.x;      // 0..3
    const int n  = blockIdx.y;      // 0..31
    const int t  = threadIdx.x;
    const int kp = t >> 5, cl = t & 31;

    const float* bp = g_outk + (size_t)n * KK * CC + cq * 32 + cl;
    float s = 0.f;
#pragma unroll
    for (int kk = 0; kk < 16; kk++)
        s += bp[(kp * 16 + kk) * CC];
    accs[kp][cl] = s;
    __syncthreads();
    if (t < 32)
        out[n * CC + cq * 32 + t] = accs[0][t] + accs[1][t]
                                  + accs[2][t] + accs[3][t];
}

// ---------------------------------------------------------------------------
extern "C" void kernel_launch(void* const* d_in, const int* in_sizes, int n_in,
                              void* d_out, int out_size)
{
    const float* x      = (const float*)d_in[0];  // [32,128,64,64]
    const float* conv_w = (const float*)d_in[1];  // [64,128]
    const float* conv_b = (const float*)d_in[2];  // [64]
    const float* cent   = (const float*)d_in[3];  // [64,128]
    const float* fc_w   = (const float*)d_in[4];  // [1,64]
    float* out = (float*)d_out;                   // [32,128]

    cudaFuncSetAttribute(netvlad_k1,
                         cudaFuncAttributeMaxDynamicSharedMemorySize,
                         SMEM_BYTES);

    netvlad_winit<<<8, 256>>>(conv_w);

    dim3 g1(NCHUNK, NN);        // 288 blocks -> balanced 2/SM
    netvlad_k1<<<g1, THREADS, SMEM_BYTES>>>(x, conv_b);

    dim3 g2a(KK, NN);
    netvlad_k2a<<<g2a, 128>>>(cent, fc_w);

    dim3 g2b(4, NN);
    netvlad_k2b<<<g2b, 128>>>(out);
}

// round 15
// speedup vs baseline: 1.5075x; 1.3160x over previous
#include <cuda_runtime.h>
#include <cstdint>
#include <math.h>

#define NN 32
#define CC 128
#define SSZ 4096
#define KK 64
#define NCHUNK 9            // chunk 0: 8 subtiles, chunks 1-8: 7 subtiles
#define SUBT 64
#define THREADS 256

// padded row lengths (floats)
#define XPADF 136
#define WPADF 136
#define APADF 72

// smem byte offsets
#define OFF_XS   0          // xs [64 p][136]  : 34816
#define OFF_WS   34816      // wk [64 k][136]  : 34816
#define OFF_AS   69632      // as [64 k][72]   : 18432
#define OFF_RED  88064      // 256 floats
#define OFF_BS   89088      // 64 floats (conv_b)
#define OFF_SMS  89856      // 128 floats (sum exchange)
#define OFF_ASR  90368      // 256 floats
#define SMEM_BYTES 91392    // 89.25 KB -> 2 blocks/SM

// scratch (no allocation allowed)
__device__ float g_vlad_part[NN * NCHUNK * KK * CC];   // [n][ch][k][c]
__device__ float g_asum_part[NN * NCHUNK * KK];
__device__ float g_outk[NN * KK * CC];                 // scaled vlad rows

// ---------------------------------------------------------------------------
__device__ __forceinline__ float tf32r(float x) {
    float r;
    asm("cvt.rna.tf32.f32 %0, %1;" : "=f"(r) : "f"(x));
    return r;
}
__device__ __forceinline__ void mma_tf32(float* d, uint32_t a0, uint32_t a1,
                                         uint32_t a2, uint32_t a3,
                                         uint32_t b0, uint32_t b1) {
    asm volatile(
        "mma.sync.aligned.m16n8k8.row.col.f32.tf32.tf32.f32 "
        "{%0,%1,%2,%3}, {%4,%5,%6,%7}, {%8,%9}, {%0,%1,%2,%3};"
        : "+f"(d[0]), "+f"(d[1]), "+f"(d[2]), "+f"(d[3])
        : "r"(a0), "r"(a1), "r"(a2), "r"(a3), "r"(b0), "r"(b1));
}
// column permutation within 8-blocks: logical j -> position 2*(j&3) + (j>>2)
__device__ __forceinline__ int perm8(int j) { return 2 * (j & 3) + ((j >> 2) & 1); }

// ---------------------------------------------------------------------------
// Kernel 1: per (n, chunk).  Raw-x pipeline (R10-proven): normalization
// deferred to the logit scale (rv) and folded into the stored a (a_s = a*rv).
// ---------------------------------------------------------------------------
__global__ void __launch_bounds__(THREADS, 2)
netvlad_k1(const float* __restrict__ x,
           const float* __restrict__ conv_w,
           const float* __restrict__ conv_b)
{
    extern __shared__ char smem[];
    float* red  = (float*)(smem + OFF_RED);
    float* bs   = (float*)(smem + OFF_BS);
    float* sms  = (float*)(smem + OFF_SMS);
    float* asr  = (float*)(smem + OFF_ASR);

    const int tid  = threadIdx.x;
    const int wid  = tid >> 5, lane = tid & 31;
    const int g    = lane >> 2, tg = lane & 3;
    const int tgh  = tg >> 1;            // store-order flip selector
    const int pg   = perm8(g);
    const int ch   = blockIdx.x, n = blockIdx.y;
    const int p    = tid & 63;           // pixel within subtile
    const int c0   = (tid >> 6) * 32;    // channel quarter
    // GEMM1 roles: 4 p-strips (16) x 2 k-halves (32)
    const int pw   = wid & 3,  kh = wid >> 2;
    const int p0   = pw * 16,  kb = kh * 32;
    // GEMM2 roles: 2 k-strips (32) x 4 c-quarters (32)
    const int mw   = wid & 1,  nh = wid >> 1;

    const int nsub = (ch == 0) ? 8 : 7;
    const int ps   = (ch == 0) ? 0 : (64 + 448 * ch);   // chunk pixel start

    // ---- prologue: issue loads for subtile 0 first (deep latency) ----
    const float* xbase = x + ((size_t)(n * CC + c0)) * SSZ + ps + p;
    float xv[32];
#pragma unroll
    for (int i = 0; i < 32; i++) xv[i] = xbase[(size_t)i * SSZ];

    // W -> smem [k][perm(c)] tf32
    for (int idx = tid; idx < KK * CC; idx += THREADS) {
        int k = idx >> 7, c = idx & 127;
        int pos = (c & ~7) + perm8(c);
        *(float*)(smem + OFF_WS + (k * WPADF + pos) * 4) = tf32r(conv_w[idx]);
    }
    if (tid < KK) bs[tid] = conv_b[tid];

    float vacc[2][4][4];
#pragma unroll
    for (int m = 0; m < 2; m++)
#pragma unroll
        for (int i = 0; i < 4; i++)
#pragma unroll
            for (int j = 0; j < 4; j++) vacc[m][i][j] = 0.f;
    float ap[8];
#pragma unroll
    for (int i = 0; i < 8; i++) ap[i] = 0.f;

#pragma unroll 1
    for (int st = 0; st < nsub; ++st) {
        // ---- sumsq of current tile (loads landed during prev GEMMs) ----
        float ssum = 0.f;
#pragma unroll
        for (int i = 0; i < 32; i++) ssum += xv[i] * xv[i];

        __syncthreads();     // S_A: prev GEMM2 done -> xs/as writable
        red[tid] = ssum;

        // ---- store RAW x (tf32), no rv dependency ----
        {
            char* rowp = smem + OFF_XS + (p * XPADF + c0) * 4;
#pragma unroll
            for (int b = 0; b < 4; b++) {
                float4 s1 = make_float4(tf32r(xv[8*b+0]), tf32r(xv[8*b+4]),
                                        tf32r(xv[8*b+1]), tf32r(xv[8*b+5]));
                float4 s2 = make_float4(tf32r(xv[8*b+2]), tf32r(xv[8*b+6]),
                                        tf32r(xv[8*b+3]), tf32r(xv[8*b+7]));
                *(float4*)(rowp + b * 32)      = s1;
                *(float4*)(rowp + b * 32 + 16) = s2;
            }
        }

        // ---- prefetch next subtile into xv (hidden behind GEMMs) ----
        if (st + 1 < nsub) {
            const float* xp2 = xbase + (st + 1) * SUBT;
#pragma unroll
            for (int i = 0; i < 32; i++) xv[i] = xp2[(size_t)i * SSZ];
        }
        __syncthreads();     // S_B: xs + red visible (also W on first iter)

        // ---- GEMM1: lac[p0..p0+15][kb..kb+31] = W · x  (raw) ----
        float lac[4][4];
#pragma unroll
        for (int i = 0; i < 4; i++)
#pragma unroll
            for (int j = 0; j < 4; j++) lac[i][j] = 0.f;
#pragma unroll
        for (int ks = 0; ks < 16; ks++) {
            uint2 aLo = *(uint2*)(smem + OFF_XS + (((p0 + g)     * XPADF) + ks * 8 + 2 * tg) * 4);
            uint2 aHi = *(uint2*)(smem + OFF_XS + (((p0 + g + 8) * XPADF) + ks * 8 + 2 * tg) * 4);
#pragma unroll
            for (int nb = 0; nb < 4; nb++) {
                uint2 bb = *(uint2*)(smem + OFF_WS + (((kb + nb * 8 + g) * WPADF) + ks * 8 + 2 * tg) * 4);
                mma_tf32(lac[nb], aLo.x, aHi.x, aLo.y, aHi.y, bb.x, bb.y);
            }
        }

        // ---- per-row inverse norms (from red) ----
        const int r0 = p0 + g, r1 = p0 + g + 8;
        const float rv0 = 1.0f / fmaxf(
            sqrtf(red[r0] + red[r0 + 64] + red[r0 + 128] + red[r0 + 192]), 1e-12f);
        const float rv1 = 1.0f / fmaxf(
            sqrtf(red[r1] + red[r1 + 64] + red[r1 + 128] + red[r1 + 192]), 1e-12f);

        // ---- softmax over full k (pairwise exchange, named barrier) ----
        {
            float v0[8], v1[8];
            float s0a = 0.f, s1a = 0.f;
#pragma unroll
            for (int i = 0; i < 8; i++) {
                int nb = i >> 1, j = i & 1;
                const float bv = bs[kb + nb * 8 + tg * 2 + j];
                v0[i] = __expf(lac[nb][j]     * rv0 + bv);  s0a += v0[i];
                v1[i] = __expf(lac[nb][2 + j] * rv1 + bv);  s1a += v1[i];
            }
            s0a += __shfl_xor_sync(0xffffffffu, s0a, 1);
            s0a += __shfl_xor_sync(0xffffffffu, s0a, 2);
            s1a += __shfl_xor_sync(0xffffffffu, s1a, 1);
            s1a += __shfl_xor_sync(0xffffffffu, s1a, 2);
            if (tg == 0) {
                sms[kh * 64 + r0] = s0a;
                sms[kh * 64 + r1] = s1a;
            }
            // only the two paired k-half warps (wid = pw, pw+4) need to meet
            asm volatile("bar.sync %0, 64;" :: "r"(1 + pw) : "memory");
            const float ir0 = 1.0f / (sms[r0] + sms[64 + r0]);
            const float ir1 = 1.0f / (sms[r1] + sms[64 + r1]);

            // a for asum; a*rv (tf32) for GEMM2.  Conflict-free store order.
#pragma unroll
            for (int nt = 0; nt < 4; nt++) {
                float a00 = v0[nt * 2 + 0] * ir0;
                float a01 = v0[nt * 2 + 1] * ir0;
                float a10 = v1[nt * 2 + 0] * ir1;
                float a11 = v1[nt * 2 + 1] * ir1;
                ap[nt * 2 + 0] += a00 + a10;
                ap[nt * 2 + 1] += a01 + a11;
                const int kA = kb + nt * 8 + tg * 2 + tgh;
                const int kB = kb + nt * 8 + tg * 2 + (1 - tgh);
                const float sA0 = tf32r((tgh ? a01 : a00) * rv0);
                const float sA1 = tf32r((tgh ? a11 : a10) * rv1);
                const float sB0 = tf32r((tgh ? a00 : a01) * rv0);
                const float sB1 = tf32r((tgh ? a10 : a11) * rv1);
                *(float*)(smem + OFF_AS + (kA * APADF + p0 + pg) * 4)     = sA0;
                *(float*)(smem + OFF_AS + (kA * APADF + p0 + 8 + pg) * 4) = sA1;
                *(float*)(smem + OFF_AS + (kB * APADF + p0 + pg) * 4)     = sB0;
                *(float*)(smem + OFF_AS + (kB * APADF + p0 + 8 + pg) * 4) = sB1;
            }
        }
        __syncthreads();     // S_C: as visible to GEMM2 consumers

        // ---- GEMM2: vlad[mw*32..+31][nh*32..+31] += a_s · x ----
#pragma unroll
        for (int ks = 0; ks < 8; ks++) {
            uint2 aL0 = *(uint2*)(smem + OFF_AS + (((mw * 32 + g)      * APADF) + ks * 8 + 2 * tg) * 4);
            uint2 aH0 = *(uint2*)(smem + OFF_AS + (((mw * 32 + g + 8)  * APADF) + ks * 8 + 2 * tg) * 4);
            uint2 aL1 = *(uint2*)(smem + OFF_AS + (((mw * 32 + g + 16) * APADF) + ks * 8 + 2 * tg) * 4);
            uint2 aH1 = *(uint2*)(smem + OFF_AS + (((mw * 32 + g + 24) * APADF) + ks * 8 + 2 * tg) * 4);
#pragma unroll
            for (int nb = 0; nb < 4; nb++) {
                const int col = nh * 32 + nb * 8 + pg;
                uint32_t b0 = *(uint32_t*)(smem + OFF_XS + (((ks * 8 + tg)     * XPADF) + col) * 4);
                uint32_t b1 = *(uint32_t*)(smem + OFF_XS + (((ks * 8 + tg + 4) * XPADF) + col) * 4);
                mma_tf32(vacc[0][nb], aL0.x, aH0.x, aL0.y, aH0.y, b0, b1);
                mma_tf32(vacc[1][nb], aL1.x, aH1.x, aL1.y, aH1.y, b0, b1);
            }
        }
    }

    // ---- write vlad partials ----
    {
        float* vp = g_vlad_part + (size_t)(n * NCHUNK + ch) * KK * CC;
#pragma unroll
        for (int m = 0; m < 2; m++) {
            const int k0 = mw * 32 + m * 16 + g;
#pragma unroll
            for (int nt = 0; nt < 4; nt++) {
                const int c = nh * 32 + nt * 8 + tg * 2;
                *(float2*)&vp[k0 * CC + c]       = make_float2(vacc[m][nt][0], vacc[m][nt][1]);
                *(float2*)&vp[(k0 + 8) * CC + c] = make_float2(vacc[m][nt][2], vacc[m][nt][3]);
            }
        }
    }
    // ---- asum reduce ----
#pragma unroll
    for (int i = 0; i < 8; i++) {
        ap[i] += __shfl_xor_sync(0xffffffffu, ap[i], 4);
        ap[i] += __shfl_xor_sync(0xffffffffu, ap[i], 8);
        ap[i] += __shfl_xor_sync(0xffffffffu, ap[i], 16);
    }
    if (lane < 4) {   // lane == tg
#pragma unroll
        for (int i = 0; i < 8; i++)
            asr[wid * 32 + (i >> 1) * 8 + lane * 2 + (i & 1)] = ap[i];
    }
    __syncthreads();
    if (tid < KK) {
        const int kh2 = tid >> 5, lk = tid & 31;
        float t = 0.f;
#pragma unroll
        for (int pw2 = 0; pw2 < 4; pw2++)
            t += asr[(kh2 * 4 + pw2) * 32 + lk];
        g_asum_part[(n * NCHUNK + ch) * KK + tid] = t;
    }
}

// ---------------------------------------------------------------------------
// Kernel 2a: one block per (n,k). Reduce chunk partials, centroid subtract,
// intra-normalize, scale by fc_w.
// ---------------------------------------------------------------------------
__global__ void __launch_bounds__(128)
netvlad_k2a(const float* __restrict__ centroids,
            const float* __restrict__ fc_w)
{
    const int k = blockIdx.x;       // 0..63
    const int n = blockIdx.y;       // 0..31
    const int c = threadIdx.x;      // 0..127
    __shared__ float sred[4];

    float asum = 0.f;
#pragma unroll
    for (int chn = 0; chn < NCHUNK; chn++)
        asum += __ldg(&g_asum_part[(n * NCHUNK + chn) * KK + k]);

    float v = -asum * centroids[k * CC + c];
#pragma unroll
    for (int chn = 0; chn < NCHUNK; chn++)
        v += g_vlad_part[((size_t)(n * NCHUNK + chn) * KK + k) * CC + c];

    float ss = v * v;
#pragma unroll
    for (int off = 16; off > 0; off >>= 1)
        ss += __shfl_xor_sync(0xffffffffu, ss, off);
    if ((c & 31) == 0) sred[c >> 5] = ss;
    __syncthreads();
    const float tot = sred[0] + sred[1] + sred[2] + sred[3];
    const float sc = (1.0f / fmaxf(sqrtf(tot), 1e-12f)) * fc_w[k];
    g_outk[((size_t)n * KK + k) * CC + c] = v * sc;
}

// ---------------------------------------------------------------------------
// Kernel 2b: out[n][c] = sum_k g_outk[n][k][c].  128 blocks (4 c-quarters
// per image), coalesced, 16-deep MLP per thread.
// ---------------------------------------------------------------------------
__global__ void __launch_bounds__(128)
netvlad_k2b(float* __restrict__ out)
{
    __shared__ float accs[4][33];
    const int cq = blockIdx.x;      // 0..3
    const int n  = blockIdx.y;      // 0..31
    const int t  = threadIdx.x;
    const int kp = t >> 5, cl = t & 31;

    const float* bp = g_outk + (size_t)n * KK * CC + cq * 32 + cl;
    float s = 0.f;
#pragma unroll
    for (int kk = 0; kk < 16; kk++)
        s += bp[(kp * 16 + kk) * CC];
    accs[kp][cl] = s;
    __syncthreads();
    if (t < 32)
        out[n * CC + cq * 32 + t] = accs[0][t] + accs[1][t]
                                  + accs[2][t] + accs[3][t];
}

// ---------------------------------------------------------------------------
extern "C" void kernel_launch(void* const* d_in, const int* in_sizes, int n_in,
                              void* d_out, int out_size)
{
    const float* x      = (const float*)d_in[0];  // [32,128,64,64]
    const float* conv_w = (const float*)d_in[1];  // [64,128]
    const float* conv_b = (const float*)d_in[2];  // [64]
    const float* cent   = (const float*)d_in[3];  // [64,128]
    const float* fc_w   = (const float*)d_in[4];  // [1,64]
    float* out = (float*)d_out;                   // [32,128]

    cudaFuncSetAttribute(netvlad_k1,
                         cudaFuncAttributeMaxDynamicSharedMemorySize,
                         SMEM_BYTES);

    dim3 g1(NCHUNK, NN);        // 288 blocks -> balanced 2/SM
    netvlad_k1<<<g1, THREADS, SMEM_BYTES>>>(x, conv_w, conv_b);

    dim3 g2a(KK, NN);
    netvlad_k2a<<<g2a, 128>>>(cent, fc_w);

    dim3 g2b(4, NN);
    netvlad_k2b<<<g2b, 128>>>(out);
}